// round 15
// baseline (speedup 1.0000x reference)
#include <cuda_runtime.h>
#include <cuda_bf16.h>
#include <math.h>

// Problem constants (fixed shapes per reference)
#define NN    100000      // total nodes
#define BB    50          // graphs
#define NPG   2000        // nodes per graph
#define FF    64          // input features
#define HH    64          // hidden
#define EE    1600000     // edges
#define EPG   (EE / BB)   // 32000 edges per graph (graph-contiguous by construction)
#define NBANDS 3
#define NZF   2400000     // framelet nnz
#define NZPG  (NZF / BB)  // 48000 nz per graph (graph-contiguous)
#define NCC   10          // classes
#define HALFN (NN / 2)    // 50000 rows per chain (25 graphs)
#define HALFG (BB / 2)    // 25 graphs per chain
#define TPAD  17          // padded floats per tile row (bank-conflict-free)
#define TILE_SMEM (NPG * TPAD * 4)   // 136000 bytes

// ---------------- static scratch (no allocation allowed) ----------------
__device__ __align__(256) float g_bufA[(size_t)NN * HH];
__device__ __align__(256) float g_bufB[(size_t)NN * HH];
__device__ __align__(256) float g_dinv[NN];
__device__ __align__(256) int2  g_offcnt[NN];     // {csr offset, degree}
__device__ __align__(256) int   g_col[EE];
__device__ __align__(256) float g_w[(size_t)NN * NBANDS];

// ---------------- build1: per-graph hist + scan -> g_offcnt, g_dinv ----------
__global__ void __launch_bounds__(1024, 1)
build1_kernel(const int* __restrict__ erow) {
    __shared__ int hcnt[NPG];        // 8 KB
    __shared__ int warp_part[32];
    __shared__ int warp_off[32];
    int g = blockIdx.x;
    int t = threadIdx.x;
    int lane = t & 31, warp = t >> 5;
    int node0 = g * NPG;
    int ebase = g * EPG;

    for (int i = t; i < NPG; i += 1024) hcnt[i] = 0;
    __syncthreads();

    for (int i = t * 4; i < EPG; i += 1024 * 4) {
        int4 r = *(const int4*)(erow + ebase + i);
        atomicAdd(&hcnt[r.x - node0], 1);
        atomicAdd(&hcnt[r.y - node0], 1);
        atomicAdd(&hcnt[r.z - node0], 1);
        atomicAdd(&hcnt[r.w - node0], 1);
    }
    __syncthreads();

    int c0 = 0, c1 = 0, s = 0;
    if (t < NPG / 2) {
        c0 = hcnt[2 * t];
        c1 = hcnt[2 * t + 1];
        s = c0 + c1;
    }
    int incl = s;
    for (int d = 1; d < 32; d <<= 1) {
        int u = __shfl_up_sync(0xffffffff, incl, d);
        if (lane >= d) incl += u;
    }
    if (lane == 31) warp_part[warp] = incl;
    __syncthreads();
    if (t < 32) {
        int x = warp_part[t];
        int wincl = x;
        for (int d = 1; d < 32; d <<= 1) {
            int u = __shfl_up_sync(0xffffffff, wincl, d);
            if (t >= d) wincl += u;
        }
        warp_off[t] = wincl - x;
    }
    __syncthreads();
    if (t < NPG / 2) {
        int excl = (incl - s) + warp_off[warp];
        int base = ebase + excl;
        int r = node0 + 2 * t;
        g_offcnt[r]     = make_int2(base, c0);
        g_offcnt[r + 1] = make_int2(base + c0, c1);
        g_dinv[r]     = rsqrtf((float)(c0 + 1));
        g_dinv[r + 1] = rsqrtf((float)(c1 + 1));
    }
}

// ---------------- build2: per-graph scatter with smem counters ---------------
__global__ void __launch_bounds__(1024, 1)
build2_kernel(const int* __restrict__ erow, const int* __restrict__ ecol) {
    __shared__ int cur[NPG];         // 8 KB
    int g = blockIdx.x;
    int t = threadIdx.x;
    int node0 = g * NPG;
    int ebase = g * EPG;

    for (int i = t; i < NPG; i += 1024) cur[i] = g_offcnt[node0 + i].x;
    __syncthreads();

    for (int i = t * 4; i < EPG; i += 1024 * 4) {
        int4 r = *(const int4*)(erow + ebase + i);
        int4 c = *(const int4*)(ecol + ebase + i);
        int p0 = atomicAdd(&cur[r.x - node0], 1);
        int p1 = atomicAdd(&cur[r.y - node0], 1);
        int p2 = atomicAdd(&cur[r.z - node0], 1);
        int p3 = atomicAdd(&cur[r.w - node0], 1);
        g_col[p0] = c.x;
        g_col[p1] = c.y;
        g_col[p2] = c.z;
        g_col[p3] = c.w;
    }
}

// ---------------- GEMM: Y[r] = dinv[r] * (X[r] @ W) on rows [row0,row0+nr) ---
__global__ void gemm64_kernel(const float* __restrict__ X, const float* __restrict__ W,
                              float* __restrict__ Y, int row0, int nr) {
    __shared__ float Ws[64 * 64];
    __shared__ float Xs[64][65];
    int t = threadIdx.x;
    int rbase = row0 + blockIdx.x * 64;
    int rows = min(64, row0 + nr - rbase);

    for (int i = t; i < 1024; i += 256)
        ((float4*)Ws)[i] = ((const float4*)W)[i];
    for (int i = t; i < rows * 64; i += 256) {
        int r = i >> 6, c = i & 63;
        Xs[r][c] = X[(size_t)(rbase + r) * 64 + c];
    }
    __syncthreads();

    int r = t & 63;
    int cg = t >> 6;            // 0..3 -> 16 columns each
    if (r < rows) {
        float acc[16];
#pragma unroll
        for (int j = 0; j < 16; j++) acc[j] = 0.0f;
#pragma unroll 8
        for (int k = 0; k < 64; k++) {
            float a = Xs[r][k];
            const float4* wr = (const float4*)(Ws + k * 64 + cg * 16);
#pragma unroll
            for (int j = 0; j < 4; j++) {
                float4 w = wr[j];
                acc[4 * j + 0] += a * w.x;
                acc[4 * j + 1] += a * w.y;
                acc[4 * j + 2] += a * w.z;
                acc[4 * j + 3] += a * w.w;
            }
        }
        float dv = g_dinv[rbase + r];
        float4* yp = (float4*)(Y + (size_t)(rbase + r) * 64 + cg * 16);
#pragma unroll
        for (int j = 0; j < 4; j++)
            yp[j] = make_float4(dv * acc[4 * j], dv * acc[4 * j + 1],
                                dv * acc[4 * j + 2], dv * acc[4 * j + 3]);
    }
}

// ---------------- smem-tiled GCN aggregation + bias + relu -------------------
// 3 blocks per graph; each block stages the graph's 16-feature slice of hin
// (2000 x 16 floats, padded to 17) in smem and gathers neighbors from smem
// instead of L2. 4 feature-quarters per block. Half-warp (16 lanes) per row.
__global__ void __launch_bounds__(1024, 1)
agg_smem_kernel(const float* __restrict__ hin, float* __restrict__ hout,
                const float* __restrict__ bias, int gfirst) {
    extern __shared__ float tile[];   // NPG * TPAD floats
    int g = gfirst + blockIdx.x / 3;
    int part = blockIdx.x % 3;
    int node0 = g * NPG;
    int bstart = (part * NPG) / 3;
    int bcnt = ((part + 1) * NPG) / 3 - bstart;
    int t = threadIdx.x;
    int warp = t >> 5;
    int half = (t >> 4) & 1;
    int lane16 = t & 15;

    for (int q = 0; q < 4; q++) {
        // stage this graph's 16-feature slice (coalesced float4 reads)
        for (int i = t; i < NPG * 4; i += 1024) {
            int n = i >> 2, c4 = (i & 3) * 4;
            float4 v = *(const float4*)(hin + (size_t)(node0 + n) * 64 + q * 16 + c4);
            float* dst = tile + n * TPAD + c4;
            dst[0] = v.x; dst[1] = v.y; dst[2] = v.z; dst[3] = v.w;
        }
        __syncthreads();

        float b = bias[q * 16 + lane16];
        for (int pr = warp; pr * 2 < bcnt; pr += 32) {
            if (pr * 2 + half < bcnt) {
                int lr = bstart + pr * 2 + half;
                int grow = node0 + lr;
                int2 oc = g_offcnt[grow];
                float a0 = 0.f, a1 = 0.f;
                int k = 0;
                for (; k + 1 < oc.y; k += 2) {
                    int c0 = __ldg(&g_col[oc.x + k]) - node0;
                    int c1 = __ldg(&g_col[oc.x + k + 1]) - node0;
                    a0 += tile[c0 * TPAD + lane16];
                    a1 += tile[c1 * TPAD + lane16];
                }
                if (k < oc.y) {
                    int c = __ldg(&g_col[oc.x + k]) - node0;
                    a0 += tile[c * TPAD + lane16];
                }
                a0 += a1 + tile[lr * TPAD + lane16];   // + self loop
                float o = fmaxf(g_dinv[grow] * a0 + b, 0.f);
                hout[(size_t)grow * 64 + q * 16 + lane16] = o;
            }
        }
        __syncthreads();
    }
}

// ---------------- fallback GCN aggregation (L2 gather, proven R14 path) ------
__global__ void agg_kernel(const float* __restrict__ hin, float* __restrict__ hout,
                           const float* __restrict__ bias, int row0, int nr) {
    int warp = (blockIdx.x * blockDim.x + threadIdx.x) >> 5;
    if (warp >= nr) return;
    int lane = threadIdx.x & 31;
    int grp  = lane >> 4;        // 0 or 1
    int fo   = lane & 15;        // float4 slot within row
    int row = row0 + warp;
    int2 oc = g_offcnt[row];
    int off = oc.x;
    int cnt = oc.y;
    float4 a0 = make_float4(0.f, 0.f, 0.f, 0.f);
    float4 a1 = make_float4(0.f, 0.f, 0.f, 0.f);
    int k = grp;
    for (; k + 2 < cnt; k += 4) {
        int c0 = __ldg(&g_col[off + k]);
        int c1 = __ldg(&g_col[off + k + 2]);
        float4 v0 = *(const float4*)(hin + (size_t)c0 * 64 + fo * 4);
        float4 v1 = *(const float4*)(hin + (size_t)c1 * 64 + fo * 4);
        a0.x += v0.x; a0.y += v0.y; a0.z += v0.z; a0.w += v0.w;
        a1.x += v1.x; a1.y += v1.y; a1.z += v1.z; a1.w += v1.w;
    }
    for (; k < cnt; k += 2) {
        int c = __ldg(&g_col[off + k]);
        float4 v = *(const float4*)(hin + (size_t)c * 64 + fo * 4);
        a0.x += v.x; a0.y += v.y; a0.z += v.z; a0.w += v.w;
    }
    if (grp == 0) {
        float4 v = *(const float4*)(hin + (size_t)row * 64 + fo * 4);
        a0.x += v.x; a0.y += v.y; a0.z += v.z; a0.w += v.w;
    }
    a0.x += a1.x; a0.y += a1.y; a0.z += a1.z; a0.w += a1.w;
    a0.x += __shfl_down_sync(0xffffffff, a0.x, 16);
    a0.y += __shfl_down_sync(0xffffffff, a0.y, 16);
    a0.z += __shfl_down_sync(0xffffffff, a0.z, 16);
    a0.w += __shfl_down_sync(0xffffffff, a0.w, 16);
    if (grp == 0) {
        float di = g_dinv[row];
        float4 b = *(const float4*)(bias + fo * 4);
        float4 o;
        o.x = fmaxf(di * a0.x + b.x, 0.f);
        o.y = fmaxf(di * a0.y + b.y, 0.f);
        o.z = fmaxf(di * a0.z + b.z, 0.f);
        o.w = fmaxf(di * a0.w + b.w, 0.f);
        *(float4*)(hout + (size_t)row * 64 + fo * 4) = o;
    }
}

// ---------------- framelet node-band weights (independent of GCN path) -------
__global__ void __launch_bounds__(1024, 1)
frame_kernel(const int* __restrict__ frow, const int* __restrict__ fcol,
             const float* __restrict__ fval, const int* __restrict__ dindex) {
    __shared__ float ws[NPG * NBANDS];   // 24 KB
    int g = blockIdx.x;
    int t = threadIdx.x;
    int node0 = g * NPG;
    for (int i = t; i < NPG * NBANDS; i += 1024) ws[i] = 0.0f;
    __syncthreads();
    int base = g * NZPG;
    for (int i = t; i < NZPG; i += 1024) {
        int k = base + i;
        int band = __ldg(&dindex[frow[k]]);
        int c = fcol[k] - node0;
        atomicAdd(&ws[c * NBANDS + band], fval[k]);
    }
    __syncthreads();
    float* dst = g_w + (size_t)g * NPG * NBANDS;
    for (int i = t; i < (NPG * NBANDS) / 4; i += 1024)
        ((float4*)dst)[i] = ((const float4*)ws)[i];
}

// ---------------- pool + MLP head (fused, one block per graph) ---------------
__global__ void __launch_bounds__(1024, 1)
tail_kernel(const float* __restrict__ h,
            const float* __restrict__ fcW1, const float* __restrict__ fcb1,
            const float* __restrict__ fcW2, const float* __restrict__ fcb2,
            float* __restrict__ out) {
    __shared__ float ws[NPG * NBANDS];         // 24 KB
    __shared__ float partial[5 * NBANDS * HH]; // 3.75 KB
    __shared__ float xs[NBANDS * HH];
    __shared__ float hid[HH];

    int g = blockIdx.x;
    int t = threadIdx.x;
    int node0 = g * NPG;

    const float* src = g_w + (size_t)g * NPG * NBANDS;
    for (int i = t; i < (NPG * NBANDS) / 4; i += 1024)
        ((float4*)ws)[i] = ((const float4*)src)[i];
    __syncthreads();

    if (t < 960) {
        int grp = t / 192;
        int p   = t % 192;
        int band = p / 64, f = p % 64;
        float acc = 0.0f;
        for (int nd = grp; nd < NPG; nd += 5)
            acc += ws[nd * NBANDS + band] * __ldg(&h[(size_t)(node0 + nd) * 64 + f]);
        partial[grp * 192 + p] = acc;
    }
    __syncthreads();
    if (t < 192) {
        xs[t] = partial[t] + partial[192 + t] + partial[384 + t]
              + partial[576 + t] + partial[768 + t];
    }
    __syncthreads();

    if (t < HH) {
        float acc = fcb1[t];
#pragma unroll 8
        for (int k = 0; k < NBANDS * HH; k++)
            acc += xs[k] * fcW1[k * HH + t];
        hid[t] = fmaxf(acc, 0.0f);
    }
    __syncthreads();
    if (t < NCC) {
        float o = fcb2[t];
#pragma unroll 8
        for (int k = 0; k < HH; k++)
            o += hid[k] * fcW2[k * NCC + t];
        out[g * NCC + t] = o;
    }
}

// ---------------- streams/events + smem attribute (static init) --------------
struct StreamPack {
    cudaStream_t sB = nullptr, sC = nullptr;
    cudaEvent_t  ev0 = nullptr, evD = nullptr, evB = nullptr, evC = nullptr;
    cudaEvent_t  evS = nullptr, evE = nullptr;
    bool ok = false;
    bool smem_ok = false;
    StreamPack() {
        if (cudaStreamCreateWithFlags(&sB, cudaStreamNonBlocking) != cudaSuccess) return;
        if (cudaStreamCreateWithFlags(&sC, cudaStreamNonBlocking) != cudaSuccess) return;
        if (cudaEventCreateWithFlags(&ev0, cudaEventDisableTiming) != cudaSuccess) return;
        if (cudaEventCreateWithFlags(&evD, cudaEventDisableTiming) != cudaSuccess) return;
        if (cudaEventCreateWithFlags(&evB, cudaEventDisableTiming) != cudaSuccess) return;
        if (cudaEventCreateWithFlags(&evC, cudaEventDisableTiming) != cudaSuccess) return;
        if (cudaEventCreateWithFlags(&evS, cudaEventDisableTiming) != cudaSuccess) return;
        if (cudaEventCreateWithFlags(&evE, cudaEventDisableTiming) != cudaSuccess) return;
        ok = true;
        smem_ok = (cudaFuncSetAttribute(agg_smem_kernel,
                     cudaFuncAttributeMaxDynamicSharedMemorySize, TILE_SMEM) == cudaSuccess);
    }
};
static StreamPack g_sp;

// ---------------- launch ----------------
extern "C" void kernel_launch(void* const* d_in, const int* in_sizes, int n_in,
                              void* d_out, int out_size) {
    const float* x         = (const float*)d_in[0];
    const int*   ei        = (const int*)  d_in[1];   // [2, E]: rows then cols
    const int*   frow      = (const int*)  d_in[3];
    const int*   fcol      = (const int*)  d_in[4];
    const float* fval      = (const float*)d_in[5];
    const int*   dindex    = (const int*)  d_in[6];
    const float* W1        = (const float*)d_in[8];
    const float* b1        = (const float*)d_in[9];
    const float* W2        = (const float*)d_in[10];
    const float* b2        = (const float*)d_in[11];
    const float* fcW1      = (const float*)d_in[12];
    const float* fcb1      = (const float*)d_in[13];
    const float* fcW2      = (const float*)d_in[14];
    const float* fcb2      = (const float*)d_in[15];
    float* out = (float*)d_out;

    const int* erow = ei;
    const int* ecol = ei + EE;

    float* bufA; cudaGetSymbolAddress((void**)&bufA, g_bufA);
    float* bufB; cudaGetSymbolAddress((void**)&bufB, g_bufB);

    bool par = g_sp.ok;
    bool sm  = g_sp.ok && g_sp.smem_ok;
    const int AGG_BLKS  = (HALFN * 32 + 255) / 256;   // per-chain fallback agg grid
    const int GEMM_BLKS = (HALFN + 63) / 64;          // per-chain gemm grid

    if (par) {
        // framelet weights are input-only: run from t=0 on sC
        cudaEventRecord(g_sp.ev0, 0);
        cudaStreamWaitEvent(g_sp.sC, g_sp.ev0, 0);
        frame_kernel<<<BB, 1024, 0, g_sp.sC>>>(frow, fcol, fval, dindex);
        cudaEventRecord(g_sp.evC, g_sp.sC);

        // CSR build phase 1 (all graphs) on main
        build1_kernel<<<BB, 1024>>>(erow);
        cudaEventRecord(g_sp.evD, 0);

        // gemm1 (all rows) on sB, overlapping build2
        cudaStreamWaitEvent(g_sp.sB, g_sp.evD, 0);
        gemm64_kernel<<<(NN + 63) / 64, 256, 0, g_sp.sB>>>(x, W1, bufA, 0, NN);
        cudaEventRecord(g_sp.evB, g_sp.sB);

        build2_kernel<<<BB, 1024>>>(erow, ecol);
        cudaEventRecord(g_sp.evS, 0);

        // ---- chain A (graphs 0-24) on main ----
        cudaStreamWaitEvent(0, g_sp.evB, 0);
        if (sm) agg_smem_kernel<<<HALFG * 3, 1024, TILE_SMEM>>>(bufA, bufB, b1, 0);
        else    agg_kernel<<<AGG_BLKS, 256>>>(bufA, bufB, b1, 0, HALFN);
        gemm64_kernel<<<GEMM_BLKS, 256>>>(bufB, W2, bufA, 0, HALFN);
        if (sm) agg_smem_kernel<<<HALFG * 3, 1024, TILE_SMEM>>>(bufA, bufB, b2, 0);
        else    agg_kernel<<<AGG_BLKS, 256>>>(bufA, bufB, b2, 0, HALFN);

        // ---- chain B (graphs 25-49) on sB ----
        cudaStreamWaitEvent(g_sp.sB, g_sp.evS, 0);
        if (sm) agg_smem_kernel<<<HALFG * 3, 1024, TILE_SMEM, g_sp.sB>>>(bufA, bufB, b1, HALFG);
        else    agg_kernel<<<AGG_BLKS, 256, 0, g_sp.sB>>>(bufA, bufB, b1, HALFN, HALFN);
        gemm64_kernel<<<GEMM_BLKS, 256, 0, g_sp.sB>>>(bufB, W2, bufA, HALFN, HALFN);
        if (sm) agg_smem_kernel<<<HALFG * 3, 1024, TILE_SMEM, g_sp.sB>>>(bufA, bufB, b2, HALFG);
        else    agg_kernel<<<AGG_BLKS, 256, 0, g_sp.sB>>>(bufA, bufB, b2, HALFN, HALFN);
        cudaEventRecord(g_sp.evE, g_sp.sB);

        // join both chains + framelet weights, then fused pool+head
        cudaStreamWaitEvent(0, g_sp.evE, 0);
        cudaStreamWaitEvent(0, g_sp.evC, 0);
        tail_kernel<<<BB, 1024>>>(bufB, fcW1, fcb1, fcW2, fcb2, out);
    } else {
        // serial fallback
        frame_kernel<<<BB, 1024>>>(frow, fcol, fval, dindex);
        build1_kernel<<<BB, 1024>>>(erow);
        gemm64_kernel<<<(NN + 63) / 64, 256>>>(x, W1, bufA, 0, NN);
        build2_kernel<<<BB, 1024>>>(erow, ecol);
        agg_kernel<<<(NN * 32 + 255) / 256, 256>>>(bufA, bufB, b1, 0, NN);
        gemm64_kernel<<<(NN + 63) / 64, 256>>>(bufB, W2, bufA, 0, NN);
        agg_kernel<<<(NN * 32 + 255) / 256, 256>>>(bufA, bufB, b2, 0, NN);
        tail_kernel<<<BB, 1024>>>(bufB, fcW1, fcb1, fcW2, fcb2, out);
    }
}

// round 16
// speedup vs baseline: 1.3171x; 1.3171x over previous
#include <cuda_runtime.h>
#include <cuda_bf16.h>
#include <math.h>

// Problem constants (fixed shapes per reference)
#define NN    100000      // total nodes
#define BB    50          // graphs
#define NPG   2000        // nodes per graph
#define FF    64          // input features
#define HH    64          // hidden
#define EE    1600000     // edges
#define EPG   (EE / BB)   // 32000 edges per graph (graph-contiguous by construction)
#define NSEG  2
#define SEGE  (EPG / NSEG)   // 16000 edges per segment
#define NBANDS 3
#define NZF   2400000     // framelet nnz
#define NZPG  (NZF / BB)  // 48000 nz per graph (graph-contiguous)
#define NCC   10          // classes
#define HALFN (NN / 2)    // 50000 rows per chain (25 graphs)

// ---------------- static scratch (no allocation allowed) ----------------
__device__ __align__(256) float g_bufA[(size_t)NN * HH];
__device__ __align__(256) float g_bufB[(size_t)NN * HH];
__device__ __align__(256) float g_dinv[NN];
__device__ __align__(256) int2  g_offcnt[NN];     // {csr offset, degree}
__device__ __align__(256) int   g_segoff[NSEG][NN];
__device__ __align__(256) int   g_col[EE];
__device__ __align__(256) float g_w[(size_t)NN * NBANDS];

// ---------------- streams/events ----------------
struct StreamPack {
    cudaStream_t sB = nullptr, sC = nullptr;
    cudaEvent_t  ev0 = nullptr, evD = nullptr, evB = nullptr, evC = nullptr;
    cudaEvent_t  evS = nullptr, evE = nullptr;
    bool ok = false;
    StreamPack() {
        if (cudaStreamCreateWithFlags(&sB, cudaStreamNonBlocking) != cudaSuccess) return;
        if (cudaStreamCreateWithFlags(&sC, cudaStreamNonBlocking) != cudaSuccess) return;
        if (cudaEventCreateWithFlags(&ev0, cudaEventDisableTiming) != cudaSuccess) return;
        if (cudaEventCreateWithFlags(&evD, cudaEventDisableTiming) != cudaSuccess) return;
        if (cudaEventCreateWithFlags(&evB, cudaEventDisableTiming) != cudaSuccess) return;
        if (cudaEventCreateWithFlags(&evC, cudaEventDisableTiming) != cudaSuccess) return;
        if (cudaEventCreateWithFlags(&evS, cudaEventDisableTiming) != cudaSuccess) return;
        if (cudaEventCreateWithFlags(&evE, cudaEventDisableTiming) != cudaSuccess) return;
        ok = true;
    }
};
static StreamPack g_sp;

// ---------------- build1: per-graph 2-segment hist + scan --------------------
// Produces g_offcnt, g_dinv, g_segoff (per-segment scatter start offsets).
__global__ void __launch_bounds__(1024, 1)
build1_kernel(const int* __restrict__ erow) {
    __shared__ int hcnt[NSEG][NPG];    // 16 KB
    __shared__ int warp_part[32];
    __shared__ int warp_off[32];
    int g = blockIdx.x;
    int t = threadIdx.x;
    int lane = t & 31, warp = t >> 5;
    int node0 = g * NPG;
    int ebase = g * EPG;

    for (int i = t; i < NSEG * NPG; i += 1024) ((int*)hcnt)[i] = 0;
    __syncthreads();

    // histogram, 4 edges per thread (SEGE % 4 == 0 -> quads never straddle segs)
    for (int i = t * 4; i < EPG; i += 1024 * 4) {
        int seg = (i >= SEGE) ? 1 : 0;
        int4 r = *(const int4*)(erow + ebase + i);
        atomicAdd(&hcnt[seg][r.x - node0], 1);
        atomicAdd(&hcnt[seg][r.y - node0], 1);
        atomicAdd(&hcnt[seg][r.z - node0], 1);
        atomicAdd(&hcnt[seg][r.w - node0], 1);
    }
    __syncthreads();

    // block scan of node totals: threads 0..999 handle nodes {2t, 2t+1}
    int a0s0 = 0, a0s1 = 0, a1s0 = 0, a1s1 = 0, tot0 = 0, tot1 = 0, s = 0;
    if (t < NPG / 2) {
        a0s0 = hcnt[0][2 * t];
        a0s1 = hcnt[1][2 * t];
        a1s0 = hcnt[0][2 * t + 1];
        a1s1 = hcnt[1][2 * t + 1];
        tot0 = a0s0 + a0s1;
        tot1 = a1s0 + a1s1;
        s = tot0 + tot1;
    }
    int incl = s;
    for (int d = 1; d < 32; d <<= 1) {
        int u = __shfl_up_sync(0xffffffff, incl, d);
        if (lane >= d) incl += u;
    }
    if (lane == 31) warp_part[warp] = incl;
    __syncthreads();
    if (t < 32) {
        int x = warp_part[t];
        int wincl = x;
        for (int d = 1; d < 32; d <<= 1) {
            int u = __shfl_up_sync(0xffffffff, wincl, d);
            if (t >= d) wincl += u;
        }
        warp_off[t] = wincl - x;
    }
    __syncthreads();
    if (t < NPG / 2) {
        int excl = (incl - s) + warp_off[warp];
        int base = ebase + excl;
        int r = node0 + 2 * t;
        g_offcnt[r]     = make_int2(base, tot0);
        g_offcnt[r + 1] = make_int2(base + tot0, tot1);
        g_dinv[r]     = rsqrtf((float)(tot0 + 1));
        g_dinv[r + 1] = rsqrtf((float)(tot1 + 1));
        g_segoff[0][r]     = base;
        g_segoff[1][r]     = base + a0s0;
        g_segoff[0][r + 1] = base + tot0;
        g_segoff[1][r + 1] = base + tot0 + a1s0;
    }
}

// ---------------- build2: 2 blocks per graph, segmented scatter --------------
__global__ void __launch_bounds__(1024, 1)
build2_kernel(const int* __restrict__ erow, const int* __restrict__ ecol) {
    __shared__ int cur[NPG];         // 8 KB
    int g   = blockIdx.x >> 1;
    int seg = blockIdx.x & 1;
    int t = threadIdx.x;
    int node0 = g * NPG;
    int ebase = g * EPG + seg * SEGE;

    for (int i = t; i < NPG; i += 1024) cur[i] = g_segoff[seg][node0 + i];
    __syncthreads();

    for (int i = t * 4; i < SEGE; i += 1024 * 4) {
        int4 r = *(const int4*)(erow + ebase + i);
        int4 c = *(const int4*)(ecol + ebase + i);
        int p0 = atomicAdd(&cur[r.x - node0], 1);
        int p1 = atomicAdd(&cur[r.y - node0], 1);
        int p2 = atomicAdd(&cur[r.z - node0], 1);
        int p3 = atomicAdd(&cur[r.w - node0], 1);
        g_col[p0] = c.x;
        g_col[p1] = c.y;
        g_col[p2] = c.z;
        g_col[p3] = c.w;
    }
}

// ---------------- dinv-scale pass: buf[r] *= dinv[r] -------------------------
__global__ void scale_kernel(float* __restrict__ buf) {
    int i = blockIdx.x * blockDim.x + threadIdx.x;   // over NN*16 float4s
    if (i < NN * 16) {
        float d = g_dinv[i >> 4];
        float4 v = ((const float4*)buf)[i];
        v.x *= d; v.y *= d; v.z *= d; v.w *= d;
        ((float4*)buf)[i] = v;
    }
}

// ---------------- GEMM on rows [row0,row0+nr): Y = (X @ W), optional dinv ----
__global__ void gemm64_kernel(const float* __restrict__ X, const float* __restrict__ W,
                              float* __restrict__ Y, int row0, int nr, int use_dinv) {
    __shared__ float Ws[64 * 64];
    __shared__ float Xs[64][65];
    int t = threadIdx.x;
    int rbase = row0 + blockIdx.x * 64;
    int rows = min(64, row0 + nr - rbase);

    for (int i = t; i < 1024; i += 256)
        ((float4*)Ws)[i] = ((const float4*)W)[i];
    for (int i = t; i < rows * 64; i += 256) {
        int r = i >> 6, c = i & 63;
        Xs[r][c] = X[(size_t)(rbase + r) * 64 + c];
    }
    __syncthreads();

    int r = t & 63;
    int cg = t >> 6;            // 0..3 -> 16 columns each
    if (r < rows) {
        float acc[16];
#pragma unroll
        for (int j = 0; j < 16; j++) acc[j] = 0.0f;
#pragma unroll 8
        for (int k = 0; k < 64; k++) {
            float a = Xs[r][k];
            const float4* wr = (const float4*)(Ws + k * 64 + cg * 16);
#pragma unroll
            for (int j = 0; j < 4; j++) {
                float4 w = wr[j];
                acc[4 * j + 0] += a * w.x;
                acc[4 * j + 1] += a * w.y;
                acc[4 * j + 2] += a * w.z;
                acc[4 * j + 3] += a * w.w;
            }
        }
        float dv = use_dinv ? g_dinv[rbase + r] : 1.0f;
        float4* yp = (float4*)(Y + (size_t)(rbase + r) * 64 + cg * 16);
#pragma unroll
        for (int j = 0; j < 4; j++)
            yp[j] = make_float4(dv * acc[4 * j], dv * acc[4 * j + 1],
                                dv * acc[4 * j + 2], dv * acc[4 * j + 3]);
    }
}

// ---------------- GCN aggregation + bias + relu on rows [row0,row0+nr) -------
// hin rows pre-scaled by dinv. warp per row, two 16-lane groups, float4 lanes.
__global__ void agg_kernel(const float* __restrict__ hin, float* __restrict__ hout,
                           const float* __restrict__ bias, int row0, int nr) {
    int warp = (blockIdx.x * blockDim.x + threadIdx.x) >> 5;
    if (warp >= nr) return;
    int lane = threadIdx.x & 31;
    int grp  = lane >> 4;        // 0 or 1
    int fo   = lane & 15;        // float4 slot within row
    int row = row0 + warp;
    int2 oc = g_offcnt[row];
    int off = oc.x;
    int cnt = oc.y;
    float4 a0 = make_float4(0.f, 0.f, 0.f, 0.f);
    float4 a1 = make_float4(0.f, 0.f, 0.f, 0.f);
    int k = grp;
    for (; k + 2 < cnt; k += 4) {
        int c0 = __ldg(&g_col[off + k]);
        int c1 = __ldg(&g_col[off + k + 2]);
        float4 v0 = *(const float4*)(hin + (size_t)c0 * 64 + fo * 4);
        float4 v1 = *(const float4*)(hin + (size_t)c1 * 64 + fo * 4);
        a0.x += v0.x; a0.y += v0.y; a0.z += v0.z; a0.w += v0.w;
        a1.x += v1.x; a1.y += v1.y; a1.z += v1.z; a1.w += v1.w;
    }
    for (; k < cnt; k += 2) {
        int c = __ldg(&g_col[off + k]);
        float4 v = *(const float4*)(hin + (size_t)c * 64 + fo * 4);
        a0.x += v.x; a0.y += v.y; a0.z += v.z; a0.w += v.w;
    }
    if (grp == 0) {  // self loop, added once
        float4 v = *(const float4*)(hin + (size_t)row * 64 + fo * 4);
        a0.x += v.x; a0.y += v.y; a0.z += v.z; a0.w += v.w;
    }
    a0.x += a1.x; a0.y += a1.y; a0.z += a1.z; a0.w += a1.w;
    a0.x += __shfl_down_sync(0xffffffff, a0.x, 16);
    a0.y += __shfl_down_sync(0xffffffff, a0.y, 16);
    a0.z += __shfl_down_sync(0xffffffff, a0.z, 16);
    a0.w += __shfl_down_sync(0xffffffff, a0.w, 16);
    if (grp == 0) {
        float di = g_dinv[row];
        float4 b = *(const float4*)(bias + fo * 4);
        float4 o;
        o.x = fmaxf(di * a0.x + b.x, 0.f);
        o.y = fmaxf(di * a0.y + b.y, 0.f);
        o.z = fmaxf(di * a0.z + b.z, 0.f);
        o.w = fmaxf(di * a0.w + b.w, 0.f);
        *(float4*)(hout + (size_t)row * 64 + fo * 4) = o;
    }
}

// ---------------- framelet node-band weights (independent of GCN path) -------
__global__ void __launch_bounds__(1024, 1)
frame_kernel(const int* __restrict__ frow, const int* __restrict__ fcol,
             const float* __restrict__ fval, const int* __restrict__ dindex) {
    __shared__ float ws[NPG * NBANDS];   // 24 KB
    int g = blockIdx.x;
    int t = threadIdx.x;
    int node0 = g * NPG;
    for (int i = t; i < NPG * NBANDS; i += 1024) ws[i] = 0.0f;
    __syncthreads();
    int base = g * NZPG;
    for (int i = t; i < NZPG; i += 1024) {
        int k = base + i;
        int band = __ldg(&dindex[frow[k]]);
        int c = fcol[k] - node0;
        atomicAdd(&ws[c * NBANDS + band], fval[k]);
    }
    __syncthreads();
    float* dst = g_w + (size_t)g * NPG * NBANDS;
    for (int i = t; i < (NPG * NBANDS) / 4; i += 1024)
        ((float4*)dst)[i] = ((const float4*)ws)[i];
}

// ---------------- pool + MLP head (fused, one block per graph) ---------------
__global__ void __launch_bounds__(1024, 1)
tail_kernel(const float* __restrict__ h,
            const float* __restrict__ fcW1, const float* __restrict__ fcb1,
            const float* __restrict__ fcW2, const float* __restrict__ fcb2,
            float* __restrict__ out) {
    __shared__ float ws[NPG * NBANDS];         // 24 KB
    __shared__ float partial[5 * NBANDS * HH]; // 3.75 KB
    __shared__ float xs[NBANDS * HH];
    __shared__ float hid[HH];

    int g = blockIdx.x;
    int t = threadIdx.x;
    int node0 = g * NPG;

    const float* src = g_w + (size_t)g * NPG * NBANDS;
    for (int i = t; i < (NPG * NBANDS) / 4; i += 1024)
        ((float4*)ws)[i] = ((const float4*)src)[i];
    __syncthreads();

    if (t < 960) {
        int grp = t / 192;
        int p   = t % 192;
        int band = p / 64, f = p % 64;
        float acc = 0.0f;
        for (int nd = grp; nd < NPG; nd += 5)
            acc += ws[nd * NBANDS + band] * __ldg(&h[(size_t)(node0 + nd) * 64 + f]);
        partial[grp * 192 + p] = acc;
    }
    __syncthreads();
    if (t < 192) {
        xs[t] = partial[t] + partial[192 + t] + partial[384 + t]
              + partial[576 + t] + partial[768 + t];
    }
    __syncthreads();

    if (t < HH) {
        float acc = fcb1[t];
#pragma unroll 8
        for (int k = 0; k < NBANDS * HH; k++)
            acc += xs[k] * fcW1[k * HH + t];
        hid[t] = fmaxf(acc, 0.0f);
    }
    __syncthreads();
    if (t < NCC) {
        float o = fcb2[t];
#pragma unroll 8
        for (int k = 0; k < HH; k++)
            o += hid[k] * fcW2[k * NCC + t];
        out[g * NCC + t] = o;
    }
}

// ---------------- launch ----------------
extern "C" void kernel_launch(void* const* d_in, const int* in_sizes, int n_in,
                              void* d_out, int out_size) {
    const float* x         = (const float*)d_in[0];
    const int*   ei        = (const int*)  d_in[1];   // [2, E]: rows then cols
    const int*   frow      = (const int*)  d_in[3];
    const int*   fcol      = (const int*)  d_in[4];
    const float* fval      = (const float*)d_in[5];
    const int*   dindex    = (const int*)  d_in[6];
    const float* W1        = (const float*)d_in[8];
    const float* b1        = (const float*)d_in[9];
    const float* W2        = (const float*)d_in[10];
    const float* b2        = (const float*)d_in[11];
    const float* fcW1      = (const float*)d_in[12];
    const float* fcb1      = (const float*)d_in[13];
    const float* fcW2      = (const float*)d_in[14];
    const float* fcb2      = (const float*)d_in[15];
    float* out = (float*)d_out;

    const int* erow = ei;
    const int* ecol = ei + EE;

    float* bufA; cudaGetSymbolAddress((void**)&bufA, g_bufA);
    float* bufB; cudaGetSymbolAddress((void**)&bufB, g_bufB);

    bool par = g_sp.ok;
    const int AGG_BLKS  = (HALFN * 32 + 255) / 256;   // per-chain agg grid
    const int GEMM_BLKS = (HALFN + 63) / 64;          // per-chain gemm grid

    if (par) {
        cudaEventRecord(g_sp.ev0, 0);

        // framelet weights (input-only) on sC from t=0
        cudaStreamWaitEvent(g_sp.sC, g_sp.ev0, 0);
        frame_kernel<<<BB, 1024, 0, g_sp.sC>>>(frow, fcol, fval, dindex);
        cudaEventRecord(g_sp.evC, g_sp.sC);

        // gemm1 UNSCALED on sB from t=0 (no dinv dependency)
        cudaStreamWaitEvent(g_sp.sB, g_sp.ev0, 0);
        gemm64_kernel<<<(NN + 63) / 64, 256, 0, g_sp.sB>>>(x, W1, bufA, 0, NN, 0);

        // CSR build on main: 2-segment hist+scan, then 100-block scatter
        build1_kernel<<<BB, 1024>>>(erow);
        cudaEventRecord(g_sp.evD, 0);
        build2_kernel<<<2 * BB, 1024>>>(erow, ecol);
        cudaEventRecord(g_sp.evS, 0);

        // dinv-scale pass on sB (after gemm1 in-order, and build1 via evD)
        cudaStreamWaitEvent(g_sp.sB, g_sp.evD, 0);
        scale_kernel<<<(NN * 16 + 255) / 256, 256, 0, g_sp.sB>>>(bufA);
        cudaEventRecord(g_sp.evB, g_sp.sB);

        // ---- chain A (graphs 0-24, rows [0, HALFN)) on main ----
        cudaStreamWaitEvent(0, g_sp.evB, 0);
        agg_kernel<<<AGG_BLKS, 256>>>(bufA, bufB, b1, 0, HALFN);
        gemm64_kernel<<<GEMM_BLKS, 256>>>(bufB, W2, bufA, 0, HALFN, 1);
        agg_kernel<<<AGG_BLKS, 256>>>(bufA, bufB, b2, 0, HALFN);

        // ---- chain B (graphs 25-49, rows [HALFN, NN)) on sB ----
        cudaStreamWaitEvent(g_sp.sB, g_sp.evS, 0);
        agg_kernel<<<AGG_BLKS, 256, 0, g_sp.sB>>>(bufA, bufB, b1, HALFN, HALFN);
        gemm64_kernel<<<GEMM_BLKS, 256, 0, g_sp.sB>>>(bufB, W2, bufA, HALFN, HALFN, 1);
        agg_kernel<<<AGG_BLKS, 256, 0, g_sp.sB>>>(bufA, bufB, b2, HALFN, HALFN);
        cudaEventRecord(g_sp.evE, g_sp.sB);

        // join both chains + framelet weights, then fused pool+head
        cudaStreamWaitEvent(0, g_sp.evE, 0);
        cudaStreamWaitEvent(0, g_sp.evC, 0);
        tail_kernel<<<BB, 1024>>>(bufB, fcW1, fcb1, fcW2, fcb2, out);
    } else {
        // serial fallback
        frame_kernel<<<BB, 1024>>>(frow, fcol, fval, dindex);
        build1_kernel<<<BB, 1024>>>(erow);
        gemm64_kernel<<<(NN + 63) / 64, 256>>>(x, W1, bufA, 0, NN, 1);
        build2_kernel<<<2 * BB, 1024>>>(erow, ecol);
        agg_kernel<<<(NN * 32 + 255) / 256, 256>>>(bufA, bufB, b1, 0, NN);
        gemm64_kernel<<<(NN + 63) / 64, 256>>>(bufB, W2, bufA, 0, NN, 1);
        agg_kernel<<<(NN * 32 + 255) / 256, 256>>>(bufA, bufB, b2, 0, NN);
        tail_kernel<<<BB, 1024>>>(bufB, fcW1, fcb1, fcW2, fcb2, out);
    }
}